// round 13
// baseline (speedup 1.0000x reference)
#include <cuda_runtime.h>
#include <cuda_fp16.h>
#include <cstdint>

#define HID     64
#define SLEN    24
#define ITEMS   128
#define THREADS 256

// Precomputed tables (device globals; no allocation).
__device__ __half   g_pre1h[4096];    // fp16 pre1[t][o] = embed[t].W1[o][0:64] + b1[o]
__device__ unsigned g_w2h  [2048];    // W2 as fp16x2 pairs, row-major [n=64][k=64]
__device__ unsigned g_pre2p[131072];  // fp16x2 pair table: [t1*64+t2][32] (4096 rows x 128B)

// ---------------------------------------------------------------------------
// Precompute: ONE kernel, 64 blocks (one wave), block b owns t1 = b.
//  1) stage E [64][66] and W1 transposed [128][66] in smem
//  2) each warp computes 8 pre2 rows SIMULTANEOUSLY (W1b read once per k;
//     es broadcast via shfl; packed f32x2 FMAs) -> s_p2 [64][66] fp32
//  3) warp 0 computes pre1h row b; warp 1 converts w2h row b
//  4) pairs (b, t2): vb cached + one LDS.64 row read + coalesced 128B STG
// ---------------------------------------------------------------------------
#define PC_SMEM_FLOATS (64*66 + 128*66 + 64*66)     // 16896 floats
#define PC_SMEM_BYTES  (PC_SMEM_FLOATS * 4)         // 67584 B

__global__ __launch_bounds__(256, 1)
void precompute_all(const float* __restrict__ embed_W,
                    const float* __restrict__ W1,
                    const float* __restrict__ b1,
                    const float* __restrict__ W2)
{
    extern __shared__ float ps[];
    float* s_emb = ps;                    // [64][66]
    float* s_w1t = ps + 64 * 66;          // [128][66]: s_w1t[k*66+o] = W1[o*128+k]
    float* s_p2  = ps + 64 * 66 + 128 * 66;   // [64][66] fp32 pre2

    const int tid  = threadIdx.x;
    const int warp = tid >> 5;
    const int lane = tid & 31;
    const int b    = blockIdx.x;          // 0..63

    // stage E padded
#pragma unroll 4
    for (int f = tid; f < 4096; f += 256) {
        int t = f >> 6, k = f & 63;
        s_emb[t * 66 + k] = embed_W[f];
    }
    // stage W1 transposed
#pragma unroll 8
    for (int f = tid; f < 8192; f += 256) {
        int o = f >> 7, k = f & 127;
        s_w1t[k * 66 + o] = W1[o * 128 + k];
    }
    __syncthreads();

    // ---- GEMM: warp computes rows t = 8p + warp, p = 0..7, all at once ----
    float elo[8], ehi[8];
#pragma unroll
    for (int p = 0; p < 8; p++) {
        int t = p * 8 + warp;
        elo[p] = s_emb[t * 66 + lane];
        ehi[p] = s_emb[t * 66 + 32 + lane];
    }
    unsigned long long acc[8];
#pragma unroll
    for (int p = 0; p < 8; p++) acc[p] = 0ull;
#pragma unroll
    for (int k = 0; k < 32; k++) {
        unsigned long long w = *(const unsigned long long*)(s_w1t + (64 + k) * 66 + 2 * lane);
#pragma unroll
        for (int p = 0; p < 8; p++) {
            float es = __shfl_sync(0xffffffffu, elo[p], k);
            unsigned long long esd;
            asm("mov.b64 %0, {%1, %1};" : "=l"(esd) : "f"(es));
            asm("fma.rn.f32x2 %0, %1, %2, %0;" : "+l"(acc[p]) : "l"(w), "l"(esd));
        }
    }
#pragma unroll
    for (int k = 0; k < 32; k++) {
        unsigned long long w = *(const unsigned long long*)(s_w1t + (96 + k) * 66 + 2 * lane);
#pragma unroll
        for (int p = 0; p < 8; p++) {
            float es = __shfl_sync(0xffffffffu, ehi[p], k);
            unsigned long long esd;
            asm("mov.b64 %0, {%1, %1};" : "=l"(esd) : "f"(es));
            asm("fma.rn.f32x2 %0, %1, %2, %0;" : "+l"(acc[p]) : "l"(w), "l"(esd));
        }
    }
#pragma unroll
    for (int p = 0; p < 8; p++) {
        int t = p * 8 + warp;
        float lo, hi;
        asm("mov.b64 {%0, %1}, %2;" : "=f"(lo), "=f"(hi) : "l"(acc[p]));
        s_p2[t * 66 + 2 * lane]     = lo * 0.125f;
        s_p2[t * 66 + 2 * lane + 1] = hi * 0.125f;
    }

    // ---- warp 0: pre1h row b (W1a half + b1) ----
    if (warp == 0) {
        float e0 = s_emb[b * 66 + lane], e1 = s_emb[b * 66 + 32 + lane];
        float a0 = b1[2 * lane], a1 = b1[2 * lane + 1];
#pragma unroll
        for (int k = 0; k < 32; k++) {
            float es = __shfl_sync(0xffffffffu, e0, k);
            float2 w = *(const float2*)(s_w1t + k * 66 + 2 * lane);
            a0 = fmaf(es, w.x, a0); a1 = fmaf(es, w.y, a1);
        }
#pragma unroll
        for (int k = 0; k < 32; k++) {
            float es = __shfl_sync(0xffffffffu, e1, k);
            float2 w = *(const float2*)(s_w1t + (32 + k) * 66 + 2 * lane);
            a0 = fmaf(es, w.x, a0); a1 = fmaf(es, w.y, a1);
        }
        __half2 h = __floats2half2_rn(a0, a1);
        ((__half2*)g_pre1h)[b * 32 + lane] = h;
    }
    // ---- warp 1: w2h row b ----
    if (warp == 1) {
        __half2 h2 = __floats2half2_rn(W2[b * 64 + 2 * lane], W2[b * 64 + 2 * lane + 1]);
        g_w2h[b * 32 + lane] = *(unsigned*)&h2;
    }
    __syncthreads();

    // ---- pairs: t1 = b fixed, t2 = 8p + warp ----
    float2 vb = *(const float2*)(s_p2 + b * 66 + 2 * lane);
#pragma unroll
    for (int p = 0; p < 8; p++) {
        int t2 = p * 8 + warp;
        float2 vc = *(const float2*)(s_p2 + t2 * 66 + 2 * lane);
        __half2 h = __floats2half2_rn(vb.x + vc.x, vb.y + vc.y);
        g_pre2p[(b * 64 + t2) * 32 + lane] = *(unsigned*)&h;
    }
}

// ---------------------------------------------------------------------------
// Main kernel. smem layout (bytes):
//   [0,8192)       s_pre1h fp16 [64][64]        (128B rows)
//   [8192,17408)   s_w2    fp16 [64 rows][72]   (144B padded rows)
//   [17408,35840)  s_H     fp16 [128 rows][72]  (144B padded rows)
//   [35840,36096)  s_b2    fp32 [64]
//   [36096,68864)  s_out   fp32 [128][64] XOR-swizzled epilogue staging
// ---------------------------------------------------------------------------
#define OFF_PRE1H  0
#define OFF_W2H    8192
#define OFF_H      17408
#define OFF_B2     35840
#define OFF_OUT    36096
#define SMEM_TOTAL 68864
#define ROWB       144          // padded row stride in bytes

__global__ __launch_bounds__(THREADS, 3)
void lru_main(const int*   __restrict__ seqs,
              const int*   __restrict__ query_tok,
              const float* __restrict__ b2,
              float*       __restrict__ out,
              int B)
{
    extern __shared__ char sm[];
    unsigned* s_pre1h = (unsigned*)(sm + OFF_PRE1H);
    char*     s_w2    = sm + OFF_W2H;
    char*     s_H     = sm + OFF_H;
    float*    s_b2    = (float*)(sm + OFF_B2);
    float*    s_out   = (float*)(sm + OFF_OUT);

    const int tid  = threadIdx.x;
    const int warp = tid >> 5;
    const int lane = tid & 31;
    const int blockBase = blockIdx.x * ITEMS;

    // ---- index loads first (overlap GMEM latency with table staging) ----
    // pa = pair01 | pair23<<12 ; pb = pair45 | pair67<<12 | q<<24
    unsigned pa = 0, pb = 0;
    {
        int it = blockBase + warp * 16 + lane;
        if (lane < 16 && it < B) {
            const int* row = seqs + (size_t)it * SLEN;   // 96B stride: row+16 is 16B aligned
            int  t0  = row[15];
            int4 t14 = *(const int4*)(row + 16);
            int2 t56 = *(const int2*)(row + 20);
            int  t7  = row[22];
            int  tq  = query_tok[it];
            pa = (unsigned)(t0 * 64 + t14.x) | ((unsigned)(t14.y * 64 + t14.z) << 12);
            pb = (unsigned)(t14.w * 64 + t56.x)
               | ((unsigned)(t56.y * 64 + t7) << 12)
               | ((unsigned)tq << 24);
        }
    }

    // ---- stage tables into smem ----
    {
        const uint2* s1 = (const uint2*)g_pre1h;
#pragma unroll
        for (int i = tid; i < 1024; i += THREADS) ((uint2*)s_pre1h)[i] = s1[i];
#pragma unroll
        for (int i = tid; i < 2048; i += THREADS) {
            int n = i >> 5, kk = i & 31;
            *(unsigned*)(s_w2 + n * ROWB + kk * 4) = g_w2h[i];
        }
        if (tid < 16) ((float4*)s_b2)[tid] = ((const float4*)b2)[tid];
    }
    __syncthreads();

    // ---- gather: warp w owns items [16w, 16w+16) == its own M-tile rows ----
    // Software-pipelined: iteration m issues m+1's LDGs before processing m.
    unsigned u0, u1, u2, u3, uq;
    {
        unsigned am = __shfl_sync(0xffffffffu, pa, 0);
        unsigned bm = __shfl_sync(0xffffffffu, pb, 0);
        u0 = __ldg(&g_pre2p[((am & 0xFFFu) << 5) + lane]);
        u1 = __ldg(&g_pre2p[((am >> 12)    << 5) + lane]);
        u2 = __ldg(&g_pre2p[((bm & 0xFFFu) << 5) + lane]);
        u3 = __ldg(&g_pre2p[(((bm >> 12) & 0xFFFu) << 5) + lane]);
        uq = s_pre1h[((bm >> 24) << 5) + lane];
    }
#pragma unroll
    for (int m = 0; m < 16; m++) {
        unsigned n0, n1, n2, n3, nq;
        if (m < 15) {
            unsigned am = __shfl_sync(0xffffffffu, pa, m + 1);
            unsigned bm = __shfl_sync(0xffffffffu, pb, m + 1);
            n0 = __ldg(&g_pre2p[((am & 0xFFFu) << 5) + lane]);
            n1 = __ldg(&g_pre2p[((am >> 12)    << 5) + lane]);
            n2 = __ldg(&g_pre2p[((bm & 0xFFFu) << 5) + lane]);
            n3 = __ldg(&g_pre2p[(((bm >> 12) & 0xFFFu) << 5) + lane]);
            nq = s_pre1h[((bm >> 24) << 5) + lane];
        }
        float2 z  = __half22float2(*(const __half2*)&uq);
        float2 v0 = __half22float2(*(const __half2*)&u0);
        float2 v1 = __half22float2(*(const __half2*)&u1);
        float2 v2 = __half22float2(*(const __half2*)&u2);
        float2 v3 = __half22float2(*(const __half2*)&u3);
        z.x += v0.x + v1.x; z.y += v0.y + v1.y;
        z.x += v2.x + v3.x; z.y += v2.y + v3.y;
        z.x = fmaxf(z.x, 0.f);
        z.y = fmaxf(z.y, 0.f);
        unsigned packed;                       // lo = z.x (col 2*lane), hi = z.y
        asm("cvt.rn.f16x2.f32 %0, %1, %2;" : "=r"(packed) : "f"(z.y), "f"(z.x));
        // row = warp*16+m, cols [2*lane, 2*lane+1]; bank (36r+lane)%32 conflict-free
        *(unsigned*)(s_H + (warp * 16 + m) * ROWB + lane * 4) = packed;
        u0 = n0; u1 = n1; u2 = n2; u3 = n3; uq = nq;
    }
    __syncwarp();   // warp's own H rows visible to all its lanes

    // ---- MMA: warp computes rows [16w,16w+16) x all 64 cols via 8n x 4k HMMA ----
    const int r = lane >> 2;        // 0..7
    const int c = lane & 3;         // 0..3
    float acc[8][4];
#pragma unroll
    for (int nt = 0; nt < 8; nt++) {
        int col = 8 * nt + 2 * c;
        acc[nt][0] = s_b2[col];
        acc[nt][1] = s_b2[col + 1];
        acc[nt][2] = acc[nt][0];
        acc[nt][3] = acc[nt][1];
    }
    const char* Ab = s_H + (warp * 16 + r) * ROWB + 4 * c;
#pragma unroll
    for (int kt = 0; kt < 4; kt++) {
        unsigned a0 = *(const unsigned*)(Ab + 32 * kt);              // row r,   k0
        unsigned a1 = *(const unsigned*)(Ab + 8 * ROWB + 32 * kt);   // row r+8, k0
        unsigned a2 = *(const unsigned*)(Ab + 16 + 32 * kt);         // row r,   k0+8
        unsigned a3 = *(const unsigned*)(Ab + 8 * ROWB + 16 + 32 * kt);
#pragma unroll
        for (int nt = 0; nt < 8; nt++) {
            const char* Bb = s_w2 + (8 * nt + r) * ROWB + 4 * c + 32 * kt;
            unsigned b0 = *(const unsigned*)(Bb);        // n, k0..k0+1
            unsigned b1 = *(const unsigned*)(Bb + 16);   // n, k0+8..k0+9
            asm volatile(
                "mma.sync.aligned.m16n8k16.row.col.f32.f16.f16.f32 "
                "{%0,%1,%2,%3}, {%4,%5,%6,%7}, {%8,%9}, {%0,%1,%2,%3};"
                : "+f"(acc[nt][0]), "+f"(acc[nt][1]), "+f"(acc[nt][2]), "+f"(acc[nt][3])
                : "r"(a0), "r"(a1), "r"(a2), "r"(a3), "r"(b0), "r"(b1));
        }
    }

    // ---- epilogue: XOR-swizzled smem stage (2 wf/STS min), then coalesced STG ----
    {
        const int itemL0 = warp * 16 + r;          // local item 0..127
        const int itemL1 = itemL0 + 8;
        const int sw0 = 8 * (itemL0 & 7);
        const int sw1 = 8 * (itemL1 & 7);
#pragma unroll
        for (int nt = 0; nt < 8; nt++) {
            int col = 8 * nt + 2 * c;
            *(float2*)(s_out + itemL0 * 64 + (col ^ sw0)) = make_float2(acc[nt][0], acc[nt][1]);
            *(float2*)(s_out + itemL1 * 64 + (col ^ sw1)) = make_float2(acc[nt][2], acc[nt][3]);
        }
        __syncwarp();
        // copy-out: 8 iters, 2 items per iter; LDS.128 swizzled + STG.128 coalesced
        const int half16 = lane >> 4;              // 0..1
        const int l16    = lane & 15;              // 0..15
#pragma unroll
        for (int itp = 0; itp < 8; itp++) {
            int itemL = warp * 16 + itp * 2 + half16;
            int colw  = 4 * l16;
            float4 v  = *(const float4*)(s_out + itemL * 64 + (colw ^ (8 * (itemL & 7))));
            int itemG = blockBase + itemL;
            if (itemG < B)
                *(float4*)(out + (size_t)itemG * HID + colw) = v;
        }
    }
}

extern "C" void kernel_launch(void* const* d_in, const int* in_sizes, int n_in,
                              void* d_out, int out_size)
{
    const int*   seqs   = (const int*)  d_in[0];
    const int*   query  = (const int*)  d_in[1];
    const float* embedW = (const float*)d_in[2];
    const float* W1     = (const float*)d_in[3];
    const float* b1     = (const float*)d_in[4];
    const float* W2     = (const float*)d_in[5];
    const float* b2     = (const float*)d_in[6];
    float*       out    = (float*)d_out;

    const int B = in_sizes[0] / SLEN;

    cudaFuncSetAttribute(precompute_all, cudaFuncAttributeMaxDynamicSharedMemorySize, PC_SMEM_BYTES);
    precompute_all<<<64, 256, PC_SMEM_BYTES>>>(embedW, W1, b1, W2);

    cudaFuncSetAttribute(lru_main, cudaFuncAttributeMaxDynamicSharedMemorySize, SMEM_TOTAL);
    const int grid = (B + ITEMS - 1) / ITEMS;
    lru_main<<<grid, THREADS, SMEM_TOTAL>>>(seqs, query, b2, out, B);
}

// round 16
// speedup vs baseline: 1.1121x; 1.1121x over previous
#include <cuda_runtime.h>
#include <cuda_fp16.h>
#include <cstdint>

#define HID     64
#define SLEN    24
#define ITEMS   128
#define THREADS 256

// Precomputed tables (device globals; no allocation).
__device__ float    g_pre2 [4096];    // fp32 pre2[t][o] = 0.125*embed[t].W1[o][64:128]
__device__ __half   g_pre1h[4096];    // fp16 pre1[t][o] = embed[t].W1[o][0:64] + b1[o]
__device__ unsigned g_w2h  [2048];    // W2 as fp16x2 pairs, row-major [n=64][k=64]
__device__ unsigned g_pre2p[131072];  // fp16x2 pair table: [t1*64+t2][32] (4096 rows x 128B)

// ---------------------------------------------------------------------------
// Precompute 1 (massively parallel, latency-tolerant): one warp per (t,o).
// Writes g_pre2 (fp32), g_pre1h (fp16), g_w2h (fp16x2).
// ---------------------------------------------------------------------------
__global__ void precompute_kernel(const float* __restrict__ embed_W,
                                  const float* __restrict__ W1,
                                  const float* __restrict__ b1,
                                  const float* __restrict__ W2)
{
    int warpId = (blockIdx.x * blockDim.x + threadIdx.x) >> 5;   // 0..4095
    int lane   = threadIdx.x & 31;
    int t = warpId >> 6;
    int o = warpId & 63;
    const float* e   = embed_W + t * HID;
    const float* w1o = W1 + o * (2 * HID);
    float e1 = e[lane], e2 = e[lane + 32];
    float s1 = e1 * w1o[lane]      + e2 * w1o[lane + 32];
    float s2 = e1 * w1o[64 + lane] + e2 * w1o[96 + lane];
#pragma unroll
    for (int d = 16; d > 0; d >>= 1) {
        s1 += __shfl_xor_sync(0xffffffffu, s1, d);
        s2 += __shfl_xor_sync(0xffffffffu, s2, d);
    }
    if (lane == 0) {
        g_pre1h[warpId] = __float2half(s1 + b1[o]);
        g_pre2 [warpId] = s2 * 0.125f;
    }
    int flat = blockIdx.x * blockDim.x + threadIdx.x;
    if (flat < 2048) {
        int n = flat >> 5, kk = flat & 31;
        __half2 h2 = __floats2half2_rn(W2[n * 64 + 2 * kk], W2[n * 64 + 2 * kk + 1]);
        g_w2h[flat] = *(unsigned*)&h2;
    }
}

// ---------------------------------------------------------------------------
// Precompute 2: pair-add. Thread -> uint2 (4 halfs) of one pair row.
//   flat2 = pair*16 + d8 ; loads float4 from row t1 and row t2 (L2-hot).
// ---------------------------------------------------------------------------
__global__ void pair_kernel()
{
    int flat2 = blockIdx.x * blockDim.x + threadIdx.x;     // 0..65535
    int pair = flat2 >> 4;
    int d8   = flat2 & 15;
    int t1 = pair >> 6, t2 = pair & 63;
    float4 a = *(const float4*)(g_pre2 + t1 * 64 + 4 * d8);
    float4 b = *(const float4*)(g_pre2 + t2 * 64 + 4 * d8);
    __half2 h0 = __floats2half2_rn(a.x + b.x, a.y + b.y);
    __half2 h1 = __floats2half2_rn(a.z + b.z, a.w + b.w);
    ((uint2*)g_pre2p)[flat2] = make_uint2(*(unsigned*)&h0, *(unsigned*)&h1);
}

// ---------------------------------------------------------------------------
// Main kernel (UNCHANGED from R13 best: 34.9us). smem layout (bytes):
//   [0,8192)       s_pre1h fp16 [64][64]        (128B rows)
//   [8192,17408)   s_w2    fp16 [64 rows][72]   (144B padded rows)
//   [17408,35840)  s_H     fp16 [128 rows][72]  (144B padded rows)
//   [35840,36096)  s_b2    fp32 [64]
//   [36096,68864)  s_out   fp32 [128][64] XOR-swizzled epilogue staging
// ---------------------------------------------------------------------------
#define OFF_PRE1H  0
#define OFF_W2H    8192
#define OFF_H      17408
#define OFF_B2     35840
#define OFF_OUT    36096
#define SMEM_TOTAL 68864
#define ROWB       144          // padded row stride in bytes

__global__ __launch_bounds__(THREADS, 3)
void lru_main(const int*   __restrict__ seqs,
              const int*   __restrict__ query_tok,
              const float* __restrict__ b2,
              float*       __restrict__ out,
              int B)
{
    extern __shared__ char sm[];
    unsigned* s_pre1h = (unsigned*)(sm + OFF_PRE1H);
    char*     s_w2    = sm + OFF_W2H;
    char*     s_H     = sm + OFF_H;
    float*    s_b2    = (float*)(sm + OFF_B2);
    float*    s_out   = (float*)(sm + OFF_OUT);

    const int tid  = threadIdx.x;
    const int warp = tid >> 5;
    const int lane = tid & 31;
    const int blockBase = blockIdx.x * ITEMS;

    // ---- index loads first (overlap GMEM latency with table staging) ----
    // pa = pair01 | pair23<<12 ; pb = pair45 | pair67<<12 | q<<24
    unsigned pa = 0, pb = 0;
    {
        int it = blockBase + warp * 16 + lane;
        if (lane < 16 && it < B) {
            const int* row = seqs + (size_t)it * SLEN;   // 96B stride: row+16 is 16B aligned
            int  t0  = row[15];
            int4 t14 = *(const int4*)(row + 16);
            int2 t56 = *(const int2*)(row + 20);
            int  t7  = row[22];
            int  tq  = query_tok[it];
            pa = (unsigned)(t0 * 64 + t14.x) | ((unsigned)(t14.y * 64 + t14.z) << 12);
            pb = (unsigned)(t14.w * 64 + t56.x)
               | ((unsigned)(t56.y * 64 + t7) << 12)
               | ((unsigned)tq << 24);
        }
    }

    // ---- stage tables into smem ----
    {
        const uint2* s1 = (const uint2*)g_pre1h;
#pragma unroll
        for (int i = tid; i < 1024; i += THREADS) ((uint2*)s_pre1h)[i] = s1[i];
#pragma unroll
        for (int i = tid; i < 2048; i += THREADS) {
            int n = i >> 5, kk = i & 31;
            *(unsigned*)(s_w2 + n * ROWB + kk * 4) = g_w2h[i];
        }
        if (tid < 16) ((float4*)s_b2)[tid] = ((const float4*)b2)[tid];
    }
    __syncthreads();

    // ---- gather: warp w owns items [16w, 16w+16) == its own M-tile rows ----
    // Software-pipelined: iteration m issues m+1's LDGs before processing m.
    unsigned u0, u1, u2, u3, uq;
    {
        unsigned am = __shfl_sync(0xffffffffu, pa, 0);
        unsigned bm = __shfl_sync(0xffffffffu, pb, 0);
        u0 = __ldg(&g_pre2p[((am & 0xFFFu) << 5) + lane]);
        u1 = __ldg(&g_pre2p[((am >> 12)    << 5) + lane]);
        u2 = __ldg(&g_pre2p[((bm & 0xFFFu) << 5) + lane]);
        u3 = __ldg(&g_pre2p[(((bm >> 12) & 0xFFFu) << 5) + lane]);
        uq = s_pre1h[((bm >> 24) << 5) + lane];
    }
#pragma unroll
    for (int m = 0; m < 16; m++) {
        unsigned n0, n1, n2, n3, nq;
        if (m < 15) {
            unsigned am = __shfl_sync(0xffffffffu, pa, m + 1);
            unsigned bm = __shfl_sync(0xffffffffu, pb, m + 1);
            n0 = __ldg(&g_pre2p[((am & 0xFFFu) << 5) + lane]);
            n1 = __ldg(&g_pre2p[((am >> 12)    << 5) + lane]);
            n2 = __ldg(&g_pre2p[((bm & 0xFFFu) << 5) + lane]);
            n3 = __ldg(&g_pre2p[(((bm >> 12) & 0xFFFu) << 5) + lane]);
            nq = s_pre1h[((bm >> 24) << 5) + lane];
        }
        float2 z  = __half22float2(*(const __half2*)&uq);
        float2 v0 = __half22float2(*(const __half2*)&u0);
        float2 v1 = __half22float2(*(const __half2*)&u1);
        float2 v2 = __half22float2(*(const __half2*)&u2);
        float2 v3 = __half22float2(*(const __half2*)&u3);
        z.x += v0.x + v1.x; z.y += v0.y + v1.y;
        z.x += v2.x + v3.x; z.y += v2.y + v3.y;
        z.x = fmaxf(z.x, 0.f);
        z.y = fmaxf(z.y, 0.f);
        unsigned packed;                       // lo = z.x (col 2*lane), hi = z.y
        asm("cvt.rn.f16x2.f32 %0, %1, %2;" : "=r"(packed) : "f"(z.y), "f"(z.x));
        // row = warp*16+m, cols [2*lane, 2*lane+1]; bank (36r+lane)%32 conflict-free
        *(unsigned*)(s_H + (warp * 16 + m) * ROWB + lane * 4) = packed;
        u0 = n0; u1 = n1; u2 = n2; u3 = n3; uq = nq;
    }
    __syncwarp();   // warp's own H rows visible to all its lanes

    // ---- MMA: warp computes rows [16w,16w+16) x all 64 cols via 8n x 4k HMMA ----
    const int r = lane >> 2;        // 0..7
    const int c = lane & 3;         // 0..3
    float acc[8][4];
#pragma unroll
    for (int nt = 0; nt < 8; nt++) {
        int col = 8 * nt + 2 * c;
        acc[nt][0] = s_b2[col];
        acc[nt][1] = s_b2[col + 1];
        acc[nt][2] = acc[nt][0];
        acc[nt][3] = acc[nt][1];
    }
    const char* Ab = s_H + (warp * 16 + r) * ROWB + 4 * c;
#pragma unroll
    for (int kt = 0; kt < 4; kt++) {
        unsigned a0 = *(const unsigned*)(Ab + 32 * kt);              // row r,   k0
        unsigned a1 = *(const unsigned*)(Ab + 8 * ROWB + 32 * kt);   // row r+8, k0
        unsigned a2 = *(const unsigned*)(Ab + 16 + 32 * kt);         // row r,   k0+8
        unsigned a3 = *(const unsigned*)(Ab + 8 * ROWB + 16 + 32 * kt);
#pragma unroll
        for (int nt = 0; nt < 8; nt++) {
            const char* Bb = s_w2 + (8 * nt + r) * ROWB + 4 * c + 32 * kt;
            unsigned b0 = *(const unsigned*)(Bb);        // n, k0..k0+1
            unsigned b1 = *(const unsigned*)(Bb + 16);   // n, k0+8..k0+9
            asm volatile(
                "mma.sync.aligned.m16n8k16.row.col.f32.f16.f16.f32 "
                "{%0,%1,%2,%3}, {%4,%5,%6,%7}, {%8,%9}, {%0,%1,%2,%3};"
                : "+f"(acc[nt][0]), "+f"(acc[nt][1]), "+f"(acc[nt][2]), "+f"(acc[nt][3])
                : "r"(a0), "r"(a1), "r"(a2), "r"(a3), "r"(b0), "r"(b1));
        }
    }

    // ---- epilogue: XOR-swizzled smem stage (2 wf/STS min), then coalesced STG ----
    {
        const int itemL0 = warp * 16 + r;          // local item 0..127
        const int itemL1 = itemL0 + 8;
        const int sw0 = 8 * (itemL0 & 7);
        const int sw1 = 8 * (itemL1 & 7);
#pragma unroll
        for (int nt = 0; nt < 8; nt++) {
            int col = 8 * nt + 2 * c;
            *(float2*)(s_out + itemL0 * 64 + (col ^ sw0)) = make_float2(acc[nt][0], acc[nt][1]);
            *(float2*)(s_out + itemL1 * 64 + (col ^ sw1)) = make_float2(acc[nt][2], acc[nt][3]);
        }
        __syncwarp();
        // copy-out: 8 iters, 2 items per iter; LDS.128 swizzled + STG.128 coalesced
        const int half16 = lane >> 4;              // 0..1
        const int l16    = lane & 15;              // 0..15
#pragma unroll
        for (int itp = 0; itp < 8; itp++) {
            int itemL = warp * 16 + itp * 2 + half16;
            int colw  = 4 * l16;
            float4 v  = *(const float4*)(s_out + itemL * 64 + (colw ^ (8 * (itemL & 7))));
            int itemG = blockBase + itemL;
            if (itemG < B)
                *(float4*)(out + (size_t)itemG * HID + colw) = v;
        }
    }
}

extern "C" void kernel_launch(void* const* d_in, const int* in_sizes, int n_in,
                              void* d_out, int out_size)
{
    const int*   seqs   = (const int*)  d_in[0];
    const int*   query  = (const int*)  d_in[1];
    const float* embedW = (const float*)d_in[2];
    const float* W1     = (const float*)d_in[3];
    const float* b1     = (const float*)d_in[4];
    const float* W2     = (const float*)d_in[5];
    const float* b2     = (const float*)d_in[6];
    float*       out    = (float*)d_out;

    const int B = in_sizes[0] / SLEN;

    precompute_kernel<<<512, 256>>>(embedW, W1, b1, W2);
    pair_kernel<<<256, 256>>>();

    cudaFuncSetAttribute(lru_main, cudaFuncAttributeMaxDynamicSharedMemorySize, SMEM_TOTAL);
    const int grid = (B + ITEMS - 1) / ITEMS;
    lru_main<<<grid, THREADS, SMEM_TOTAL>>>(seqs, query, b2, out, B);
}